// round 2
// baseline (speedup 1.0000x reference)
#include <cuda_runtime.h>

#define NF 39
#define NV 200000
#define NE 16
#define ND 32
#define NB 16384
#define RPB 128            // rows per block
#define NT 512             // 4 threads per row (e-quarters)

// ---------- f32x2 packed helpers (sm_103a FFMA2 path, PTX-only) ----------
static __device__ __forceinline__ unsigned long long pack2(float a, float b) {
    unsigned long long r;
    asm("mov.b64 %0, {%1, %2};" : "=l"(r) : "f"(a), "f"(b));
    return r;
}
static __device__ __forceinline__ unsigned long long splat2(float a) {
    unsigned long long r;
    asm("mov.b64 %0, {%1, %1};" : "=l"(r) : "f"(a));
    return r;
}
static __device__ __forceinline__ void ffma2(unsigned long long& acc,
                                             unsigned long long a,
                                             unsigned long long b) {
    asm("fma.rn.f32x2 %0, %1, %2, %0;" : "+l"(acc) : "l"(a), "l"(b));
}
static __device__ __forceinline__ void unpack2(unsigned long long v, float& lo, float& hi) {
    asm("mov.b64 {%0, %1}, %2;" : "=f"(lo), "=f"(hi) : "l"(v));
}

// ---------- smem layout (bytes) ----------
#define W_PAIRS   (NF * ND * NE)            // 19968 ulonglongs = 159744 B
#define OFF_MLP   (W_PAIRS * 8)
#define MLP_FLOATS 2176
#define OFF_X     (OFF_MLP + MLP_FLOATS * 4)
#define XB_FLOATS (RPB * 33)
#define OFF_Y     (OFF_X + XB_FLOATS * 4)
#define SMEM_TOTAL (OFF_Y + XB_FLOATS * 4)   // 202240 bytes

extern __shared__ unsigned char smem_raw[];

__global__ void __launch_bounds__(NT, 1)
pnn_kernel(const int* __restrict__ Xi, const float* __restrict__ Xv,
           const float* __restrict__ tables,
           const float* __restrict__ W1, const float* __restrict__ Wi,
           const float* __restrict__ l1w, const float* __restrict__ l1b,
           const float* __restrict__ l2w, const float* __restrict__ l2b,
           const float* __restrict__ lw, const float* __restrict__ lb,
           float* __restrict__ out)
{
    unsigned long long* Wp = reinterpret_cast<unsigned long long*>(smem_raw);
    float* mlp  = reinterpret_cast<float*>(smem_raw + OFF_MLP);
    float* xbuf = reinterpret_cast<float*>(smem_raw + OFF_X);
    float* ybuf = reinterpret_cast<float*>(smem_raw + OFF_Y);

    const int tid = threadIdx.x;

    // ---- stage packed weights: Wp[(f*32 + d)*16 + e] = {W1[d,f,e], Wi[d,f,e]} ----
    for (int i = tid; i < W_PAIRS; i += NT) {
        int f = i >> 9;            // i / 512
        int rr = i & 511;
        int d = rr >> 4;
        int e = rr & 15;
        int g = d * (NF * NE) + f * NE + e;
        Wp[i] = pack2(W1[g], Wi[g]);
    }
    // ---- stage MLP weights ----
    for (int i = tid; i < 1024; i += NT) { mlp[i] = l1w[i]; mlp[1024 + i] = l2w[i]; }
    if (tid < 32) {
        mlp[2048 + tid] = l1b[tid];
        mlp[2080 + tid] = l2b[tid];
        mlp[2112 + tid] = lw[tid];
        if (tid == 0) mlp[2144] = lb[0];
    }
    __syncthreads();

    const int q   = tid & 3;       // e-quarter (lane-adjacent within warp)
    const int r   = tid >> 2;      // local row 0..127
    const int row = blockIdx.x * RPB + r;

    const int*   xi = Xi + row * NF;
    const float* xv = Xv + row * NF;

    // 32 packed accumulators: lane0 = first_order(d), lane1 = s(d) — partial over this e-quarter
    unsigned long long acc[ND];
#pragma unroll
    for (int d = 0; d < ND; d++) acc[d] = 0ull;

    const ulonglong2* W2 = reinterpret_cast<const ulonglong2*>(Wp);

    // preload field 0's quarter (one LDG.128 per thread)
    int   idx0 = xi[0];
    float vcur = xv[0];
    float4 t = reinterpret_cast<const float4*>(tables + (long)idx0 * NE)[q];

    for (int f = 0; f < NF; f++) {
        // prefetch next field's quarter
        int   fn  = (f + 1 < NF) ? (f + 1) : (NF - 1);
        int   idn = xi[fn];
        float vnext = xv[fn];
        float4 tn = reinterpret_cast<const float4*>(
            tables + ((long)fn * NV + (long)idn) * NE)[q];

        // 4 emb values of this quarter, Xv-scaled, splatted to both f32x2 lanes
        unsigned long long e0 = splat2(t.x * vcur);
        unsigned long long e1 = splat2(t.y * vcur);
        unsigned long long e2 = splat2(t.z * vcur);
        unsigned long long e3 = splat2(t.w * vcur);

        const int base = (f * ND) * 8 + 2 * q;   // ulonglong2 index for d=0
#pragma unroll
        for (int d = 0; d < ND; d++) {
            ulonglong2 wa = W2[base + d * 8];       // e = 4q, 4q+1  (16B, conflict-free)
            ulonglong2 wb = W2[base + d * 8 + 1];   // e = 4q+2, 4q+3
            ffma2(acc[d], e0, wa.x);
            ffma2(acc[d], e1, wa.y);
            ffma2(acc[d], e2, wb.x);
            ffma2(acc[d], e3, wb.y);
        }

        t = tn;
        vcur = vnext;
    }

    // ---- reduce e-quarters across the 4 lanes of each row (butterfly keeps all lanes full) ----
    // then x[d] = first_order + s^2; each lane writes its 8 d's
#pragma unroll
    for (int d = 0; d < ND; d++) {
        float fo, s;
        unpack2(acc[d], fo, s);
        fo += __shfl_xor_sync(0xffffffffu, fo, 1);
        s  += __shfl_xor_sync(0xffffffffu, s,  1);
        fo += __shfl_xor_sync(0xffffffffu, fo, 2);
        s  += __shfl_xor_sync(0xffffffffu, s,  2);
        if ((d >> 3) == q) xbuf[r * 33 + d] = fmaf(s, s, fo);
    }
    __syncthreads();

    // layer 1: y = relu(x @ l1w^T + b1); each lane computes its 8 outputs
    {
        const float* xr = xbuf + r * 33;
#pragma unroll
        for (int j = 0; j < 8; j++) {
            int jj = q * 8 + j;
            float s = mlp[2048 + jj];
            const float* wrow = mlp + jj * 32;
#pragma unroll
            for (int k = 0; k < 32; k++) s = fmaf(xr[k], wrow[k], s);
            ybuf[r * 33 + jj] = fmaxf(s, 0.0f);
        }
    }
    __syncthreads();

    // layer 2: z = relu(y @ l2w^T + b2) -> back into xbuf
    {
        const float* yr = ybuf + r * 33;
#pragma unroll
        for (int j = 0; j < 8; j++) {
            int jj = q * 8 + j;
            float s = mlp[2080 + jj];
            const float* wrow = mlp + 1024 + jj * 32;
#pragma unroll
            for (int k = 0; k < 32; k++) s = fmaf(yr[k], wrow[k], s);
            xbuf[r * 33 + jj] = fmaxf(s, 0.0f);
        }
    }
    __syncthreads();

    // final: out = z @ last_w^T + last_b
    if (q == 0) {
        float s = mlp[2144];
        const float* zr = xbuf + r * 33;
#pragma unroll
        for (int k = 0; k < 32; k++) s = fmaf(zr[k], mlp[2112 + k], s);
        out[row] = s;
    }
}

extern "C" void kernel_launch(void* const* d_in, const int* in_sizes, int n_in,
                              void* d_out, int out_size)
{
    const int*   Xi     = (const int*)  d_in[0];
    const float* Xv     = (const float*)d_in[1];
    const float* tables = (const float*)d_in[2];
    const float* W1     = (const float*)d_in[3];
    const float* Wi     = (const float*)d_in[4];
    const float* l1w    = (const float*)d_in[5];
    const float* l1b    = (const float*)d_in[6];
    const float* l2w    = (const float*)d_in[7];
    const float* l2b    = (const float*)d_in[8];
    const float* lw     = (const float*)d_in[9];
    const float* lb     = (const float*)d_in[10];

    cudaFuncSetAttribute(pnn_kernel, cudaFuncAttributeMaxDynamicSharedMemorySize, SMEM_TOTAL);

    pnn_kernel<<<NB / RPB, NT, SMEM_TOTAL>>>(
        Xi, Xv, tables, W1, Wi, l1w, l1b, l2w, l2b, lw, lb, (float*)d_out);
}

// round 3
// speedup vs baseline: 1.6469x; 1.6469x over previous
#include <cuda_runtime.h>

#define NF 39
#define NV 200000
#define NE 16
#define ND 32
#define NB 16384
#define FC 13            // fields per chunk
#define NCHUNK 3
#define RPB 128
#define NT1 256
#define NT2 256

// cross-kernel scratch: [chunk][k=64 (d,fo/s interleaved)][row]
static __device__ float g_scratch[NCHUNK * 64 * NB];

// ---------- f32x2 packed helpers ----------
static __device__ __forceinline__ unsigned long long pack2(float a, float b) {
    unsigned long long r;
    asm("mov.b64 %0, {%1, %2};" : "=l"(r) : "f"(a), "f"(b));
    return r;
}
static __device__ __forceinline__ unsigned long long splat2(float a) {
    unsigned long long r;
    asm("mov.b64 %0, {%1, %1};" : "=l"(r) : "f"(a));
    return r;
}
static __device__ __forceinline__ void ffma2(unsigned long long& acc,
                                             unsigned long long a,
                                             unsigned long long b) {
    asm("fma.rn.f32x2 %0, %1, %2, %0;" : "+l"(acc) : "l"(a), "l"(b));
}
static __device__ __forceinline__ void unpack2(unsigned long long v, float& lo, float& hi) {
    asm("mov.b64 {%0, %1}, %2;" : "=f"(lo), "=f"(hi) : "l"(v));
}

// ---------- K1 smem layout (bytes) ----------
// Wp  : FC*32*16 ull = 6656*8   = 53248
// buf : 2 * 128 rows * 20 floats = 20480   (row stride 20 floats -> conflict-free)
// Xi_s: 128*13 int               = 6656
// Xv_s: 128*13 float             = 6656
#define OFF_BUF 53248
#define OFF_XI  73728
#define OFF_XV  80384
#define SMEM_K1 87040

extern __shared__ unsigned char smem1[];

__global__ void __launch_bounds__(NT1, 2)
pnn_k1(const int* __restrict__ Xi, const float* __restrict__ Xv,
       const float* __restrict__ tables,
       const float* __restrict__ W1, const float* __restrict__ Wi)
{
    unsigned long long* Wp = reinterpret_cast<unsigned long long*>(smem1);
    float* buf = reinterpret_cast<float*>(smem1 + OFF_BUF);
    int*   Xis = reinterpret_cast<int*>(smem1 + OFF_XI);
    float* Xvs = reinterpret_cast<float*>(smem1 + OFF_XV);

    const int tid  = threadIdx.x;
    const int rb   = blockIdx.x & 127;
    const int fcid = blockIdx.x >> 7;          // grid = 3*128
    const int f0   = fcid * FC;

    // ---- stage packed weights for this field chunk ----
    for (int i = tid; i < FC * 512; i += NT1) {
        int fl = i >> 9, rr = i & 511, d = rr >> 4, e = rr & 15;
        int g = d * (NF * NE) + (f0 + fl) * NE + e;
        Wp[i] = pack2(W1[g], Wi[g]);
    }
    // ---- stage this block's Xi/Xv slice ----
    for (int i = tid; i < RPB * FC; i += NT1) {
        int r = i / FC, fl = i - r * FC;
        int g = (rb * RPB + r) * NF + f0 + fl;
        Xis[i] = Xi[g];
        Xvs[i] = Xv[g];
    }
    __syncthreads();

    const int gr = tid >> 1, gh = tid & 1;     // gather: 2 threads per row, 32B each
    const float4* tab4 = reinterpret_cast<const float4*>(tables);

    // ---- gather field 0 into buf[0] ----
    {
        int   idx = Xis[gr * FC];
        float v   = Xvs[gr * FC];
        const float4* src = tab4 + ((long)f0 * NV + idx) * 4 + gh * 2;
        float4 a = src[0], b = src[1];
        float4* dst = reinterpret_cast<float4*>(buf) + gr * 5 + gh * 2;
        dst[0] = make_float4(a.x * v, a.y * v, a.z * v, a.w * v);
        dst[1] = make_float4(b.x * v, b.y * v, b.z * v, b.w * v);
    }
    __syncthreads();

    const int h = tid >> 7;                    // d-half (warp-uniform)
    const int r = tid & 127;                   // lane = row within warp

    unsigned long long acc[16];
#pragma unroll
    for (int d = 0; d < 16; d++) acc[d] = 0ull;

    for (int fl = 0; fl < FC; fl++) {
        const int p = fl & 1;

        // issue next field's gather LDG early (hidden under compute)
        float4 na, nb; float nv = 0.0f;
        const bool pf = (fl + 1 < FC);
        if (pf) {
            int idx = Xis[gr * FC + fl + 1];
            nv = Xvs[gr * FC + fl + 1];
            const float4* src = tab4 + ((long)(f0 + fl + 1) * NV + idx) * 4 + gh * 2;
            na = src[0]; nb = src[1];
        }

        // ---- compute field fl from buf[p] ----
        const float4* eb = reinterpret_cast<const float4*>(buf) + p * 640 + r * 5;
        float4 e0 = eb[0], e1 = eb[1], e2 = eb[2], e3 = eb[3];
        unsigned long long sp[16];
        sp[0]  = splat2(e0.x); sp[1]  = splat2(e0.y); sp[2]  = splat2(e0.z); sp[3]  = splat2(e0.w);
        sp[4]  = splat2(e1.x); sp[5]  = splat2(e1.y); sp[6]  = splat2(e1.z); sp[7]  = splat2(e1.w);
        sp[8]  = splat2(e2.x); sp[9]  = splat2(e2.y); sp[10] = splat2(e2.z); sp[11] = splat2(e2.w);
        sp[12] = splat2(e3.x); sp[13] = splat2(e3.y); sp[14] = splat2(e3.z); sp[15] = splat2(e3.w);

        const ulonglong2* Wf =
            reinterpret_cast<const ulonglong2*>(Wp) + (fl * ND + h * 16) * 8;
#pragma unroll
        for (int d = 0; d < 16; d++) {
            const ulonglong2* w2 = Wf + d * 8;
#pragma unroll
            for (int j = 0; j < 8; j++) {
                ulonglong2 w = w2[j];          // warp-uniform broadcast LDS.128
                ffma2(acc[d], sp[2 * j],     w.x);
                ffma2(acc[d], sp[2 * j + 1], w.y);
            }
        }

        // store prefetched field
        if (pf) {
            float4* dst = reinterpret_cast<float4*>(buf) + (p ^ 1) * 640 + gr * 5 + gh * 2;
            dst[0] = make_float4(na.x * nv, na.y * nv, na.z * nv, na.w * nv);
            dst[1] = make_float4(nb.x * nv, nb.y * nv, nb.z * nv, nb.w * nv);
        }
        __syncthreads();
    }

    // ---- write partial (fo, s) to scratch, coalesced over rows ----
    const int row = rb * RPB + r;
#pragma unroll
    for (int d = 0; d < 16; d++) {
        float fo, sv;
        unpack2(acc[d], fo, sv);
        int k = (h * 16 + d) * 2;
        g_scratch[(fcid * 64 + k) * NB + row]     = fo;
        g_scratch[(fcid * 64 + k + 1) * NB + row] = sv;
    }
}

// ---------------- Kernel 2: reduce chunks + s^2 + MLP ----------------
__global__ void __launch_bounds__(NT2)
pnn_k2(const float* __restrict__ l1w, const float* __restrict__ l1b,
       const float* __restrict__ l2w, const float* __restrict__ l2b,
       const float* __restrict__ lw,  const float* __restrict__ lb,
       float* __restrict__ out)
{
    __shared__ float mlp[2176];
    __shared__ float xb[RPB * 33];
    __shared__ float yb[RPB * 33];

    const int tid = threadIdx.x;
    for (int i = tid; i < 1024; i += NT2) { mlp[i] = l1w[i]; mlp[1024 + i] = l2w[i]; }
    if (tid < 32) {
        mlp[2048 + tid] = l1b[tid];
        mlp[2080 + tid] = l2b[tid];
        mlp[2112 + tid] = lw[tid];
        if (tid == 0) mlp[2144] = lb[0];
    }
    __syncthreads();

    const int h = tid >> 7, r = tid & 127;
    const int row = blockIdx.x * RPB + r;

#pragma unroll
    for (int d = 0; d < 16; d++) {
        int k = (h * 16 + d) * 2;
        float fo = 0.0f, sv = 0.0f;
#pragma unroll
        for (int fc = 0; fc < NCHUNK; fc++) {
            fo += g_scratch[(fc * 64 + k) * NB + row];
            sv += g_scratch[(fc * 64 + k + 1) * NB + row];
        }
        xb[r * 33 + h * 16 + d] = fmaf(sv, sv, fo);
    }
    __syncthreads();

#pragma unroll
    for (int j = 0; j < 16; j++) {
        int jj = h * 16 + j;
        float s = mlp[2048 + jj];
        const float* wrow = mlp + jj * 32;
        const float* xr = xb + r * 33;
#pragma unroll
        for (int k = 0; k < 32; k++) s = fmaf(xr[k], wrow[k], s);
        yb[r * 33 + jj] = fmaxf(s, 0.0f);
    }
    __syncthreads();

#pragma unroll
    for (int j = 0; j < 16; j++) {
        int jj = h * 16 + j;
        float s = mlp[2080 + jj];
        const float* wrow = mlp + 1024 + jj * 32;
        const float* yr = yb + r * 33;
#pragma unroll
        for (int k = 0; k < 32; k++) s = fmaf(yr[k], wrow[k], s);
        xb[r * 33 + jj] = fmaxf(s, 0.0f);
    }
    __syncthreads();

    if (h == 0) {
        float s = mlp[2144];
        const float* zr = xb + r * 33;
#pragma unroll
        for (int k = 0; k < 32; k++) s = fmaf(zr[k], mlp[2112 + k], s);
        out[row] = s;
    }
}

extern "C" void kernel_launch(void* const* d_in, const int* in_sizes, int n_in,
                              void* d_out, int out_size)
{
    const int*   Xi     = (const int*)  d_in[0];
    const float* Xv     = (const float*)d_in[1];
    const float* tables = (const float*)d_in[2];
    const float* W1     = (const float*)d_in[3];
    const float* Wi     = (const float*)d_in[4];
    const float* l1w    = (const float*)d_in[5];
    const float* l1b    = (const float*)d_in[6];
    const float* l2w    = (const float*)d_in[7];
    const float* l2b    = (const float*)d_in[8];
    const float* lw     = (const float*)d_in[9];
    const float* lb     = (const float*)d_in[10];

    cudaFuncSetAttribute(pnn_k1, cudaFuncAttributeMaxDynamicSharedMemorySize, SMEM_K1);

    pnn_k1<<<NCHUNK * (NB / RPB), NT1, SMEM_K1>>>(Xi, Xv, tables, W1, Wi);
    pnn_k2<<<NB / RPB, NT2>>>(l1w, l1b, l2w, l2b, lw, lb, (float*)d_out);
}